// round 1
// baseline (speedup 1.0000x reference)
#include <cuda_runtime.h>
#include <cuda_bf16.h>
#include <math.h>

#define N_NODES 50000
#define N_EDGES 800000
// dims: IN=256, EMB1=128, EMB2=64, L1=64

// ---------------- device scratch (no allocs allowed) ----------------
__device__ float g_xr1 [(size_t)N_NODES * 128];   // x @ w_rel1^T
__device__ float g_h   [(size_t)N_NODES * 128];   // conv1 pre-activation (root+b, += agg)
__device__ float g_zr  [(size_t)N_NODES * 64];    // h' @ w_rel_mu^T
__device__ float g_zbuf[(size_t)N_NODES * 64];    // z_mu pre-tanh
__device__ float g_z   [(size_t)N_NODES * 64];    // aligned copy of z (=z_mu)
__device__ float g_gr  [(size_t)N_NODES * 64];    // z @ w_rel_g1^T
__device__ float g_gbuf[(size_t)N_NODES * 64];    // g1 pre-activation
__device__ float g_srel[N_NODES];                 // per-node scalar rel-gate msg
__device__ float g_gate[N_NODES];                 // gate pre-softmax
__device__ float g_norm[N_NODES];                 // max(||z||, eps)
__device__ float g_W1[256 * 256];                 // [rel1 ; root1]   rows x K=256
__device__ float g_W2[192 * 128];                 // [rel_mu ; root_mu ; std] x K=128
__device__ float g_W3[128 * 64];                  // [rel_g1 ; root_g1] x K=64
__device__ float g_pool[64];
__device__ float g_scal[2];                       // [0]=gate max, [1]=sum exp

__device__ __forceinline__ float lrelu(float v) { return v > 0.f ? v : 0.2f * v; }

// ---------------- weight prepack (concat W matrices) ----------------
__global__ void prepack_kernel(const float* __restrict__ wr1, const float* __restrict__ wo1,
                               const float* __restrict__ wrm, const float* __restrict__ wom,
                               const float* __restrict__ wstd,
                               const float* __restrict__ wrg1, const float* __restrict__ wog1) {
    int i = blockIdx.x * blockDim.x + threadIdx.x;  // 0 .. 65535
    if (i < 128 * 256)           g_W1[i] = wr1[i];
    else if (i < 256 * 256)      g_W1[i] = wo1[i - 128 * 256];
    if (i < 64 * 128)            g_W2[i] = wrm[i];
    else if (i < 128 * 128)      g_W2[i] = wom[i - 64 * 128];
    else if (i < 192 * 128)      g_W2[i] = wstd[i - 128 * 128];
    if (i < 64 * 64)             g_W3[i] = wrg1[i];
    else if (i < 128 * 64)       g_W3[i] = wog1[i - 64 * 64];
}

// ---------------- tiled SGEMM: C[M,NOUT] = act(A[M,K]) * W[NOUT,K]^T ----------------
// MODE 1: A=x (param), K=256, NOUT=256: cols<128 -> g_xr1 ; cols>=128 -> g_h = . + b1
// MODE 2: A=lrelu(g_h), K=128, NOUT=192: <64 -> g_zr ; <128 -> g_zbuf=.+b_mu ; else z_std out
// MODE 3: A=g_z,        K=64,  NOUT=128: <64 -> g_gr ; else g_gbuf=.+b_g1
template <int MODE>
__global__ void gemm_kernel(const float* __restrict__ Aparam,
                            const float* __restrict__ bias0,
                            const float* __restrict__ bias1,
                            float* __restrict__ out_extra) {
    constexpr int K    = (MODE == 1) ? 256 : (MODE == 2) ? 128 : 64;
    __shared__ float As[32][68];
    __shared__ float Bs[32][68];

    const float* A = (MODE == 1) ? Aparam : (MODE == 2) ? (const float*)g_h : (const float*)g_z;
    const float* W = (MODE == 1) ? (const float*)g_W1 : (MODE == 2) ? (const float*)g_W2 : (const float*)g_W3;

    int tid = threadIdx.x;            // 256 threads
    int tx = tid & 15, ty = tid >> 4;
    int row0 = blockIdx.y * 64;
    int col0 = blockIdx.x * 64;

    float acc[4][4];
#pragma unroll
    for (int i = 0; i < 4; i++)
#pragma unroll
        for (int j = 0; j < 4; j++) acc[i][j] = 0.f;

    for (int k0 = 0; k0 < K; k0 += 32) {
        // load A tile (64 rows x 32 k) as float4, store transposed into As[k][r]
#pragma unroll
        for (int i = 0; i < 2; i++) {
            int li = tid + i * 256;        // 0..511
            int r  = li >> 3;              // 0..63
            int kq = (li & 7) * 4;         // 0..28
            float4 v = make_float4(0.f, 0.f, 0.f, 0.f);
            int grow = row0 + r;
            if (grow < N_NODES)
                v = *(const float4*)&A[(size_t)grow * K + k0 + kq];
            if (MODE == 2) { v.x = lrelu(v.x); v.y = lrelu(v.y); v.z = lrelu(v.z); v.w = lrelu(v.w); }
            As[kq + 0][r] = v.x; As[kq + 1][r] = v.y; As[kq + 2][r] = v.z; As[kq + 3][r] = v.w;
        }
        // load B tile: Bs[k][j] = W[(col0+j)*K + k0+k]
#pragma unroll
        for (int i = 0; i < 2; i++) {
            int li = tid + i * 256;
            int j  = li >> 3;
            int kq = (li & 7) * 4;
            float4 v = *(const float4*)&W[(size_t)(col0 + j) * K + k0 + kq];
            Bs[kq + 0][j] = v.x; Bs[kq + 1][j] = v.y; Bs[kq + 2][j] = v.z; Bs[kq + 3][j] = v.w;
        }
        __syncthreads();
#pragma unroll
        for (int kk = 0; kk < 32; kk++) {
            float4 a = *(const float4*)&As[kk][ty * 4];
            float4 b = *(const float4*)&Bs[kk][tx * 4];
            acc[0][0] += a.x * b.x; acc[0][1] += a.x * b.y; acc[0][2] += a.x * b.z; acc[0][3] += a.x * b.w;
            acc[1][0] += a.y * b.x; acc[1][1] += a.y * b.y; acc[1][2] += a.y * b.z; acc[1][3] += a.y * b.w;
            acc[2][0] += a.z * b.x; acc[2][1] += a.z * b.y; acc[2][2] += a.z * b.z; acc[2][3] += a.z * b.w;
            acc[3][0] += a.w * b.x; acc[3][1] += a.w * b.y; acc[3][2] += a.w * b.z; acc[3][3] += a.w * b.w;
        }
        __syncthreads();
    }

#pragma unroll
    for (int i = 0; i < 4; i++) {
        int grow = row0 + ty * 4 + i;
        if (grow >= N_NODES) continue;
#pragma unroll
        for (int j = 0; j < 4; j++) {
            int gcol = col0 + tx * 4 + j;
            float v = acc[i][j];
            if (MODE == 1) {
                if (gcol < 128) g_xr1[(size_t)grow * 128 + gcol] = v;
                else            g_h  [(size_t)grow * 128 + gcol - 128] = v + bias0[gcol - 128];
            } else if (MODE == 2) {
                if (gcol < 64)       g_zr  [(size_t)grow * 64 + gcol]       = v;
                else if (gcol < 128) g_zbuf[(size_t)grow * 64 + gcol - 64]  = v + bias0[gcol - 64];
                else                 out_extra[(size_t)grow * 64 + gcol - 128] =
                                         expf(tanhf(v + bias1[gcol - 128]));
            } else {
                if (gcol < 64) g_gr  [(size_t)grow * 64 + gcol]      = v;
                else           g_gbuf[(size_t)grow * 64 + gcol - 64] = v + bias0[gcol - 64];
            }
        }
    }
}

// ---------------- edge scatters (vector red.add, L2-resident) ----------------
__device__ __forceinline__ void red_add_v4(float* p, float4 v) {
    asm volatile("red.global.add.v4.f32 [%0], {%1, %2, %3, %4};"
                 :: "l"(p), "f"(v.x), "f"(v.y), "f"(v.z), "f"(v.w) : "memory");
}

__global__ void scatter128_kernel(const int* __restrict__ row, const int* __restrict__ col) {
    long long idx = (long long)blockIdx.x * blockDim.x + threadIdx.x;
    if (idx >= (long long)N_EDGES * 32) return;
    int e = (int)(idx >> 5);
    int q = ((int)idx & 31) * 4;
    int c = __ldg(&col[e]);
    int r = __ldg(&row[e]);
    float4 v = *(const float4*)&g_xr1[(size_t)c * 128 + q];
    red_add_v4(&g_h[(size_t)r * 128 + q], v);
}

__global__ void scatter64_kernel(const int* __restrict__ row, const int* __restrict__ col, int mode) {
    long long idx = (long long)blockIdx.x * blockDim.x + threadIdx.x;
    if (idx >= (long long)N_EDGES * 16) return;
    int e = (int)(idx >> 4);
    int q = ((int)idx & 15) * 4;
    int c = __ldg(&col[e]);
    int r = __ldg(&row[e]);
    const float* src = (mode == 0) ? (const float*)g_zr : (const float*)g_gr;
    float* dst       = (mode == 0) ? (float*)g_zbuf : (float*)g_gbuf;
    float4 v = *(const float4*)&src[(size_t)c * 64 + q];
    red_add_v4(&dst[(size_t)r * 64 + q], v);
}

__global__ void scatter_gate_kernel(const int* __restrict__ row, const int* __restrict__ col) {
    int e = blockIdx.x * blockDim.x + threadIdx.x;
    if (e >= N_EDGES) return;
    atomicAdd(&g_gate[__ldg(&row[e])], g_srel[__ldg(&col[e])]);
}

// ---------------- z = tanh(zbuf); write z/z_mu outputs; per-node norm ----------------
__global__ void tanh_norm_kernel(float* __restrict__ out_z, float* __restrict__ out_zmu) {
    int n = blockIdx.x * blockDim.x + threadIdx.x;
    if (n >= N_NODES) return;
    float ss = 0.f;
#pragma unroll
    for (int i = 0; i < 16; i++) {
        float4 v = *(const float4*)&g_zbuf[(size_t)n * 64 + i * 4];
        v.x = tanhf(v.x); v.y = tanhf(v.y); v.z = tanhf(v.z); v.w = tanhf(v.w);
        ss += v.x * v.x + v.y * v.y + v.z * v.z + v.w * v.w;
        *(float4*)&g_z[(size_t)n * 64 + i * 4] = v;
        size_t o = (size_t)n * 64 + i * 4;
        out_z[o + 0] = v.x; out_z[o + 1] = v.y; out_z[o + 2] = v.z; out_z[o + 3] = v.w;
        out_zmu[o + 0] = v.x; out_zmu[o + 1] = v.y; out_zmu[o + 2] = v.z; out_zmu[o + 3] = v.w;
    }
    g_norm[n] = fmaxf(sqrtf(ss), 1e-8f);
}

// ---------------- per-edge cosine similarity ----------------
__global__ void edge_cos_kernel(const int* __restrict__ row, const int* __restrict__ col,
                                float* __restrict__ wmu) {
    int e = blockIdx.x * blockDim.x + threadIdx.x;
    if (e >= N_EDGES) return;
    int r = __ldg(&row[e]);
    int c = __ldg(&col[e]);
    const float4* a = (const float4*)&g_z[(size_t)r * 64];
    const float4* b = (const float4*)&g_z[(size_t)c * 64];
    float acc = 0.f;
#pragma unroll
    for (int i = 0; i < 16; i++) {
        float4 u = __ldg(a + i), v = __ldg(b + i);
        acc += u.x * v.x + u.y * v.y + u.z * v.z + u.w * v.w;
    }
    wmu[e] = acc / (g_norm[r] * g_norm[c]);
}

// ---------------- gate: s_rel[n]=g1.w_rel_g2, gate[n]=g1.w_root_g2+b ----------------
__global__ void gate_node_kernel(const float* __restrict__ wrel2, const float* __restrict__ wroot2,
                                 const float* __restrict__ bg2) {
    int n = blockIdx.x * blockDim.x + threadIdx.x;
    if (n >= N_NODES) return;
    float s0 = 0.f, s1 = 0.f;
#pragma unroll
    for (int j = 0; j < 64; j++) {
        float g = lrelu(g_gbuf[(size_t)n * 64 + j]);
        s0 += g * __ldg(&wrel2[j]);
        s1 += g * __ldg(&wroot2[j]);
    }
    g_srel[n] = s0;
    g_gate[n] = s1 + __ldg(&bg2[0]);
}

// ---------------- gate max (single block) + zero accumulators ----------------
__global__ void max_kernel() {
    __shared__ float sm[1024];
    int t = threadIdx.x;
    float m = -1e30f;
    for (int i = t; i < N_NODES; i += 1024) m = fmaxf(m, g_gate[i]);
    sm[t] = m;
    __syncthreads();
    for (int s = 512; s > 0; s >>= 1) {
        if (t < s) sm[t] = fmaxf(sm[t], sm[t + s]);
        __syncthreads();
    }
    if (t == 0) { g_scal[0] = sm[0]; g_scal[1] = 0.f; }
    if (t < 64) g_pool[t] = 0.f;
}

// ---------------- sum exp + weighted pool (64 threads / block, 256 nodes / block) ----------------
__global__ void pool_kernel() {
    int t = threadIdx.x;  // 0..63
    int n0 = blockIdx.x * 256;
    int n1 = n0 + 256; if (n1 > N_NODES) n1 = N_NODES;
    float gmax = g_scal[0];
    float acc = 0.f, sacc = 0.f;
    for (int n = n0; n < n1; n++) {
        float w = expf(g_gate[n] - gmax);
        acc += w * g_z[(size_t)n * 64 + t];
        if (t == 0) sacc += w;
    }
    atomicAdd(&g_pool[t], acc);
    if (t == 0) atomicAdd(&g_scal[1], sacc);
}

// ---------------- classifier + final outputs ----------------
__global__ void final_kernel(const float* __restrict__ w_cls1, const float* __restrict__ b_cls1,
                             const float* __restrict__ w_cls2, const float* __restrict__ b_cls2,
                             const float* __restrict__ log_std, float* __restrict__ out) {
    __shared__ float pooled[64], y1s[64], y2s[2];
    int t = threadIdx.x;  // 64
    pooled[t] = g_pool[t] / g_scal[1];
    __syncthreads();
    float acc = __ldg(&b_cls1[t]);
#pragma unroll
    for (int j = 0; j < 64; j++) acc += pooled[j] * __ldg(&w_cls1[t * 64 + j]);
    y1s[t] = lrelu(acc);
    __syncthreads();
    if (t < 2) {
        float a = __ldg(&b_cls2[t]);
#pragma unroll
        for (int j = 0; j < 64; j++) a += y1s[j] * __ldg(&w_cls2[t * 64 + j]);
        y2s[t] = a;
    }
    __syncthreads();
    if (t == 0) {
        float m = fmaxf(y2s[0], y2s[1]);
        float e0 = expf(y2s[0] - m), e1 = expf(y2s[1] - m);
        out[0] = e0 / (e0 + e1);
        out[1] = e1 / (e0 + e1);
        out[2 + N_EDGES] = expf(__ldg(&log_std[0]));
    }
}

// ---------------- launch ----------------
extern "C" void kernel_launch(void* const* d_in, const int* in_sizes, int n_in,
                              void* d_out, int out_size) {
    const float* x        = (const float*)d_in[0];
    const int*   row      = (const int*)d_in[1];
    const int*   col      = (const int*)d_in[2];
    const float* w_rel1   = (const float*)d_in[3];
    const float* w_root1  = (const float*)d_in[4];
    const float* b1       = (const float*)d_in[5];
    const float* w_rel_mu = (const float*)d_in[6];
    const float* w_root_mu= (const float*)d_in[7];
    const float* b_mu     = (const float*)d_in[8];
    const float* w_std    = (const float*)d_in[9];
    const float* b_std    = (const float*)d_in[10];
    const float* w_rel_g1 = (const float*)d_in[11];
    const float* w_root_g1= (const float*)d_in[12];
    const float* b_g1     = (const float*)d_in[13];
    const float* w_rel_g2 = (const float*)d_in[14];
    const float* w_root_g2= (const float*)d_in[15];
    const float* b_g2     = (const float*)d_in[16];
    const float* w_cls1   = (const float*)d_in[17];
    const float* b_cls1   = (const float*)d_in[18];
    const float* w_cls2   = (const float*)d_in[19];
    const float* b_cls2   = (const float*)d_in[20];
    const float* log_std  = (const float*)d_in[21];

    float* out       = (float*)d_out;
    float* out_wmu   = out + 2;
    float* out_z     = out + 3 + N_EDGES;
    float* out_zmu   = out_z + (size_t)N_NODES * 64;
    float* out_zstd  = out_zmu + (size_t)N_NODES * 64;

    const int MB = (N_NODES + 63) / 64;  // 782 row-blocks

    prepack_kernel<<<256, 256>>>(w_rel1, w_root1, w_rel_mu, w_root_mu, w_std, w_rel_g1, w_root_g1);

    // layer 1: h = x@rel1^T (msgs) ; h_root = x@root1^T + b1
    gemm_kernel<1><<<dim3(4, MB), 256>>>(x, b1, nullptr, nullptr);
    scatter128_kernel<<<(N_EDGES * 32 + 255) / 256, 256>>>(row, col);

    // layer 2 (+ std head): inputs lrelu(h)
    gemm_kernel<2><<<dim3(3, MB), 256>>>(nullptr, b_mu, b_std, out_zstd);
    scatter64_kernel<<<(N_EDGES * 16 + 255) / 256, 256>>>(row, col, 0);

    // z = tanh, norms, write z / z_mu outputs
    tanh_norm_kernel<<<(N_NODES + 255) / 256, 256>>>(out_z, out_zmu);

    // edge cosine similarity
    edge_cos_kernel<<<(N_EDGES + 255) / 256, 256>>>(row, col, out_wmu);

    // gating conv 1
    gemm_kernel<3><<<dim3(2, MB), 256>>>(nullptr, b_g1, nullptr, nullptr);
    scatter64_kernel<<<(N_EDGES * 16 + 255) / 256, 256>>>(row, col, 1);

    // gating conv 2 (scalar)
    gate_node_kernel<<<(N_NODES + 255) / 256, 256>>>(w_rel_g2, w_root_g2, b_g2);
    scatter_gate_kernel<<<(N_EDGES + 255) / 256, 256>>>(row, col);

    // softmax pooling + classifier
    max_kernel<<<1, 1024>>>();
    pool_kernel<<<(N_NODES + 255) / 256, 64>>>();
    final_kernel<<<1, 64>>>(w_cls1, b_cls1, w_cls2, b_cls2, log_std, out);
}

// round 2
// speedup vs baseline: 1.1549x; 1.1549x over previous
#include <cuda_runtime.h>
#include <cuda_bf16.h>
#include <math.h>

#define N_NODES 50000
#define N_EDGES 800000
// dims: IN=256, EMB1=128, EMB2=64, L1=64

// ---------------- device scratch (no allocs allowed) ----------------
__device__ float g_xr1 [(size_t)N_NODES * 128];   // x @ w_rel1^T
__device__ float g_h   [(size_t)N_NODES * 128];   // conv1: root+b then +=agg, lrelu (in-place)
__device__ float g_zr  [(size_t)N_NODES * 64];    // h @ w_rel_mu^T
__device__ float g_zbuf[(size_t)N_NODES * 64];    // root_mu + b_mu
__device__ float g_z   [(size_t)N_NODES * 64];    // z = tanh(zbuf + agg)
__device__ float g_gr  [(size_t)N_NODES * 64];    // z @ w_rel_g1^T
__device__ float g_gbuf[(size_t)N_NODES * 64];    // root_g1 + b_g1
__device__ float g_srel[N_NODES];                 // per-node scalar rel-gate msg
__device__ float g_gate[N_NODES];                 // gate pre-softmax
__device__ float g_norm[N_NODES];                 // max(||z||, eps)
__device__ float g_W1[256 * 256];                 // [rel1 ; root1]   rows x K=256
__device__ float g_W2[192 * 128];                 // [rel_mu ; root_mu ; std] x K=128
__device__ float g_W3[128 * 64];                  // [rel_g1 ; root_g1] x K=64
__device__ float g_pool[64];
__device__ float g_scal[2];                       // [0]=gate max, [1]=sum exp
// CSR scratch
__device__ int g_cnt[N_NODES];
__device__ int g_rs[N_NODES + 1];
__device__ int g_fill[N_NODES];
__device__ int g_dst[N_EDGES];

__device__ __forceinline__ float lrelu(float v) { return v > 0.f ? v : 0.2f * v; }

__device__ __forceinline__ unsigned long long dupf(float v) {
    unsigned long long r;
    asm("mov.b64 %0, {%1, %1};" : "=l"(r) : "f"(v));
    return r;
}
__device__ __forceinline__ float2 unpk(unsigned long long u) {
    float2 r;
    asm("mov.b64 {%0, %1}, %2;" : "=f"(r.x), "=f"(r.y) : "l"(u));
    return r;
}
#define FMA2(c, a, b) asm("fma.rn.f32x2 %0, %1, %2, %0;" : "+l"(c) : "l"(a), "l"(b))

// ---------------- weight prepack + CSR counter zero ----------------
__global__ void prepack_kernel(const float* __restrict__ wr1, const float* __restrict__ wo1,
                               const float* __restrict__ wrm, const float* __restrict__ wom,
                               const float* __restrict__ wstd,
                               const float* __restrict__ wrg1, const float* __restrict__ wog1) {
    int i = blockIdx.x * blockDim.x + threadIdx.x;  // 0 .. 65535
    if (i < 128 * 256)           g_W1[i] = wr1[i];
    else if (i < 256 * 256)      g_W1[i] = wo1[i - 128 * 256];
    if (i < 64 * 128)            g_W2[i] = wrm[i];
    else if (i < 128 * 128)      g_W2[i] = wom[i - 64 * 128];
    else if (i < 192 * 128)      g_W2[i] = wstd[i - 128 * 128];
    if (i < 64 * 64)             g_W3[i] = wrg1[i];
    else if (i < 128 * 64)       g_W3[i] = wog1[i - 64 * 64];
    if (i < N_NODES)             g_cnt[i] = 0;
}

// ---------------- CSR build ----------------
__global__ void hist_kernel(const int* __restrict__ row) {
    int e = blockIdx.x * blockDim.x + threadIdx.x;
    if (e < N_EDGES) atomicAdd(&g_cnt[__ldg(&row[e])], 1);
}

__global__ void scan_kernel() {
    __shared__ int part[1024];
    int t = threadIdx.x;
    const int CH = (N_NODES + 1023) / 1024;  // 49
    int base = t * CH;
    int s = 0;
    for (int i = 0; i < CH; i++) {
        int idx = base + i;
        if (idx < N_NODES) s += g_cnt[idx];
    }
    part[t] = s;
    __syncthreads();
    for (int off = 1; off < 1024; off <<= 1) {
        int v = (t >= off) ? part[t - off] : 0;
        __syncthreads();
        part[t] += v;
        __syncthreads();
    }
    int run = (t == 0) ? 0 : part[t - 1];
    for (int i = 0; i < CH; i++) {
        int idx = base + i;
        if (idx < N_NODES) {
            g_rs[idx] = run;
            g_fill[idx] = run;
            run += g_cnt[idx];
        }
    }
    if (t == 1023) g_rs[N_NODES] = part[1023];
}

__global__ void fill_kernel(const int* __restrict__ row, const int* __restrict__ col) {
    int e = blockIdx.x * blockDim.x + threadIdx.x;
    if (e >= N_EDGES) return;
    int pos = atomicAdd(&g_fill[__ldg(&row[e])], 1);
    g_dst[pos] = __ldg(&col[e]);
}

// ---------------- f32x2 SGEMM: C[128 x 64-block] = A[M,K] * W[NOUT,K]^T ----------------
// MODE 1: A=x,    K=256, col blocks 0,1 -> g_xr1 ; 2,3 -> g_h = v + b1
// MODE 2: A=g_h,  K=128, block 0 -> g_zr ; 1 -> g_zbuf = v+b_mu ; 2 -> exp(tanh(v+b_std))
// MODE 3: A=g_z,  K=64,  block 0 -> g_gr ; 1 -> g_gbuf = v+b_g1
template <int MODE>
__global__ __launch_bounds__(128)
void gemm_kernel(const float* __restrict__ Aparam,
                 const float* __restrict__ bias0,
                 const float* __restrict__ bias1,
                 float* __restrict__ out_extra) {
    constexpr int K = (MODE == 1) ? 256 : (MODE == 2) ? 128 : 64;
    constexpr int NST = K / 16;
    __shared__ unsigned long long As[2][16][130];  // dup pairs (a,a)
    __shared__ float Bs[2][16][68];

    const float* A = (MODE == 1) ? Aparam : (MODE == 2) ? (const float*)g_h : (const float*)g_z;
    const float* W = (MODE == 1) ? (const float*)g_W1 : (MODE == 2) ? (const float*)g_W2 : (const float*)g_W3;

    const int tid = threadIdx.x;
    const int tx = tid & 7, ty = tid >> 3;
    const int row0 = blockIdx.y * 128;
    const int col0 = blockIdx.x * 64;
    const int rA = tid >> 2;           // 0..31 (+32*i)
    const int kqA = (tid & 3) * 4;     // 0,4,8,12

    float4 sa[4], sb[2];
    unsigned long long acc[8][4];
#pragma unroll
    for (int i = 0; i < 8; i++)
#pragma unroll
        for (int p = 0; p < 4; p++) acc[i][p] = 0ull;

    // prologue: stage 0
#pragma unroll
    for (int i = 0; i < 4; i++) {
        int r = rA + 32 * i;
        int grow = row0 + r;
        sa[i] = (grow < N_NODES) ? *(const float4*)&A[(size_t)grow * K + kqA]
                                 : make_float4(0.f, 0.f, 0.f, 0.f);
    }
#pragma unroll
    for (int i = 0; i < 2; i++) {
        int j = rA + 32 * i;
        sb[i] = *(const float4*)&W[(size_t)(col0 + j) * K + kqA];
    }
#pragma unroll
    for (int i = 0; i < 4; i++) {
        int r = rA + 32 * i;
        As[0][kqA + 0][r] = dupf(sa[i].x);
        As[0][kqA + 1][r] = dupf(sa[i].y);
        As[0][kqA + 2][r] = dupf(sa[i].z);
        As[0][kqA + 3][r] = dupf(sa[i].w);
    }
#pragma unroll
    for (int i = 0; i < 2; i++) {
        int j = rA + 32 * i;
        Bs[0][kqA + 0][j] = sb[i].x;
        Bs[0][kqA + 1][j] = sb[i].y;
        Bs[0][kqA + 2][j] = sb[i].z;
        Bs[0][kqA + 3][j] = sb[i].w;
    }
    __syncthreads();

    for (int s = 0; s < NST; s++) {
        if (s + 1 < NST) {
            int k0 = (s + 1) * 16;
#pragma unroll
            for (int i = 0; i < 4; i++) {
                int r = rA + 32 * i;
                int grow = row0 + r;
                sa[i] = (grow < N_NODES) ? *(const float4*)&A[(size_t)grow * K + k0 + kqA]
                                         : make_float4(0.f, 0.f, 0.f, 0.f);
            }
#pragma unroll
            for (int i = 0; i < 2; i++) {
                int j = rA + 32 * i;
                sb[i] = *(const float4*)&W[(size_t)(col0 + j) * K + k0 + kqA];
            }
        }
        const int buf = s & 1;
#pragma unroll
        for (int kk = 0; kk < 16; kk++) {
            const unsigned long long* ap = &As[buf][kk][ty * 8];
            ulonglong2 a01 = *(const ulonglong2*)(ap + 0);
            ulonglong2 a23 = *(const ulonglong2*)(ap + 2);
            ulonglong2 a45 = *(const ulonglong2*)(ap + 4);
            ulonglong2 a67 = *(const ulonglong2*)(ap + 6);
            const float* bp = &Bs[buf][kk][tx * 8];
            ulonglong2 b01 = *(const ulonglong2*)(bp);
            ulonglong2 b23 = *(const ulonglong2*)(bp + 4);
            unsigned long long av[8] = {a01.x, a01.y, a23.x, a23.y, a45.x, a45.y, a67.x, a67.y};
            unsigned long long bv[4] = {b01.x, b01.y, b23.x, b23.y};
#pragma unroll
            for (int i = 0; i < 8; i++) {
#pragma unroll
                for (int p = 0; p < 4; p++) FMA2(acc[i][p], av[i], bv[p]);
            }
        }
        if (s + 1 < NST) {
            const int nb = buf ^ 1;
#pragma unroll
            for (int i = 0; i < 4; i++) {
                int r = rA + 32 * i;
                As[nb][kqA + 0][r] = dupf(sa[i].x);
                As[nb][kqA + 1][r] = dupf(sa[i].y);
                As[nb][kqA + 2][r] = dupf(sa[i].z);
                As[nb][kqA + 3][r] = dupf(sa[i].w);
            }
#pragma unroll
            for (int i = 0; i < 2; i++) {
                int j = rA + 32 * i;
                Bs[nb][kqA + 0][j] = sb[i].x;
                Bs[nb][kqA + 1][j] = sb[i].y;
                Bs[nb][kqA + 2][j] = sb[i].z;
                Bs[nb][kqA + 3][j] = sb[i].w;
            }
            __syncthreads();
        }
    }

    // epilogue
    const int cb = tx * 8;  // 0..56 within the 64-wide col block
    float4 bb0 = make_float4(0.f, 0.f, 0.f, 0.f), bb1 = bb0;
    if (MODE == 1 && blockIdx.x >= 2) {
        bb0 = *(const float4*)&bias0[col0 - 128 + cb];
        bb1 = *(const float4*)&bias0[col0 - 128 + cb + 4];
    } else if ((MODE == 2 && blockIdx.x == 1) || (MODE == 3 && blockIdx.x == 1)) {
        bb0 = *(const float4*)&bias0[cb];
        bb1 = *(const float4*)&bias0[cb + 4];
    } else if (MODE == 2 && blockIdx.x == 2) {
        bb0 = *(const float4*)&bias1[cb];
        bb1 = *(const float4*)&bias1[cb + 4];
    }

#pragma unroll
    for (int i = 0; i < 8; i++) {
        int grow = row0 + ty * 8 + i;
        if (grow >= N_NODES) continue;
        float2 p0 = unpk(acc[i][0]), p1 = unpk(acc[i][1]);
        float2 p2 = unpk(acc[i][2]), p3 = unpk(acc[i][3]);
        float4 v0 = make_float4(p0.x, p0.y, p1.x, p1.y);
        float4 v1 = make_float4(p2.x, p2.y, p3.x, p3.y);
        if (MODE == 1) {
            if (blockIdx.x < 2) {
                size_t o = (size_t)grow * 128 + col0 + cb;
                *(float4*)&g_xr1[o] = v0;
                *(float4*)&g_xr1[o + 4] = v1;
            } else {
                size_t o = (size_t)grow * 128 + (col0 - 128) + cb;
                v0.x += bb0.x; v0.y += bb0.y; v0.z += bb0.z; v0.w += bb0.w;
                v1.x += bb1.x; v1.y += bb1.y; v1.z += bb1.z; v1.w += bb1.w;
                *(float4*)&g_h[o] = v0;
                *(float4*)&g_h[o + 4] = v1;
            }
        } else if (MODE == 2) {
            size_t o = (size_t)grow * 64 + cb;
            if (blockIdx.x == 0) {
                *(float4*)&g_zr[o] = v0;
                *(float4*)&g_zr[o + 4] = v1;
            } else if (blockIdx.x == 1) {
                v0.x += bb0.x; v0.y += bb0.y; v0.z += bb0.z; v0.w += bb0.w;
                v1.x += bb1.x; v1.y += bb1.y; v1.z += bb1.z; v1.w += bb1.w;
                *(float4*)&g_zbuf[o] = v0;
                *(float4*)&g_zbuf[o + 4] = v1;
            } else {
                v0.x = expf(tanhf(v0.x + bb0.x)); v0.y = expf(tanhf(v0.y + bb0.y));
                v0.z = expf(tanhf(v0.z + bb0.z)); v0.w = expf(tanhf(v0.w + bb0.w));
                v1.x = expf(tanhf(v1.x + bb1.x)); v1.y = expf(tanhf(v1.y + bb1.y));
                v1.z = expf(tanhf(v1.z + bb1.z)); v1.w = expf(tanhf(v1.w + bb1.w));
                out_extra[o + 0] = v0.x; out_extra[o + 1] = v0.y;
                out_extra[o + 2] = v0.z; out_extra[o + 3] = v0.w;
                out_extra[o + 4] = v1.x; out_extra[o + 5] = v1.y;
                out_extra[o + 6] = v1.z; out_extra[o + 7] = v1.w;
            }
        } else {
            size_t o = (size_t)grow * 64 + cb;
            if (blockIdx.x == 0) {
                *(float4*)&g_gr[o] = v0;
                *(float4*)&g_gr[o + 4] = v1;
            } else {
                v0.x += bb0.x; v0.y += bb0.y; v0.z += bb0.z; v0.w += bb0.w;
                v1.x += bb1.x; v1.y += bb1.y; v1.z += bb1.z; v1.w += bb1.w;
                *(float4*)&g_gbuf[o] = v0;
                *(float4*)&g_gbuf[o + 4] = v1;
            }
        }
    }
}

// ---------------- CSR gathers (warp per node) ----------------
__global__ void gather_h_kernel() {
    int gw = (blockIdx.x * blockDim.x + threadIdx.x) >> 5;
    int lane = threadIdx.x & 31;
    if (gw >= N_NODES) return;
    int s = g_rs[gw], e = g_rs[gw + 1];
    float4 acc = make_float4(0.f, 0.f, 0.f, 0.f);
    for (int i = s; i < e; i++) {
        int c = __ldg(&g_dst[i]);
        float4 v = *(const float4*)&g_xr1[(size_t)c * 128 + lane * 4];
        acc.x += v.x; acc.y += v.y; acc.z += v.z; acc.w += v.w;
    }
    size_t o = (size_t)gw * 128 + lane * 4;
    float4 h = *(float4*)&g_h[o];
    h.x = lrelu(h.x + acc.x); h.y = lrelu(h.y + acc.y);
    h.z = lrelu(h.z + acc.z); h.w = lrelu(h.w + acc.w);
    *(float4*)&g_h[o] = h;
}

__global__ void gather_z_kernel(float* __restrict__ out_z, float* __restrict__ out_zmu) {
    int gw = (blockIdx.x * blockDim.x + threadIdx.x) >> 5;
    int lane = threadIdx.x & 31;
    if (gw >= N_NODES) return;
    int s = g_rs[gw], e = g_rs[gw + 1];
    float a0 = 0.f, a1 = 0.f;
    for (int i = s; i < e; i++) {
        int c = __ldg(&g_dst[i]);
        float2 v = *(const float2*)&g_zr[(size_t)c * 64 + lane * 2];
        a0 += v.x; a1 += v.y;
    }
    size_t o = (size_t)gw * 64 + lane * 2;
    float2 zb = *(const float2*)&g_zbuf[o];
    float z0 = tanhf(zb.x + a0), z1 = tanhf(zb.y + a1);
    *(float2*)&g_z[o] = make_float2(z0, z1);
    out_z[o] = z0; out_z[o + 1] = z1;       // unaligned base, scalar stores
    out_zmu[o] = z0; out_zmu[o + 1] = z1;
    float ss = z0 * z0 + z1 * z1;
#pragma unroll
    for (int off = 16; off; off >>= 1) ss += __shfl_xor_sync(0xffffffffu, ss, off);
    if (lane == 0) g_norm[gw] = fmaxf(sqrtf(ss), 1e-8f);
}

__global__ void gather_g_kernel(const float* __restrict__ wrel2, const float* __restrict__ wroot2,
                                const float* __restrict__ bg2) {
    int gw = (blockIdx.x * blockDim.x + threadIdx.x) >> 5;
    int lane = threadIdx.x & 31;
    if (gw >= N_NODES) return;
    int s = g_rs[gw], e = g_rs[gw + 1];
    float a0 = 0.f, a1 = 0.f;
    for (int i = s; i < e; i++) {
        int c = __ldg(&g_dst[i]);
        float2 v = *(const float2*)&g_gr[(size_t)c * 64 + lane * 2];
        a0 += v.x; a1 += v.y;
    }
    size_t o = (size_t)gw * 64 + lane * 2;
    float2 gb = *(const float2*)&g_gbuf[o];
    float g0 = lrelu(gb.x + a0), g1 = lrelu(gb.y + a1);
    float s0 = g0 * __ldg(&wrel2[lane * 2]) + g1 * __ldg(&wrel2[lane * 2 + 1]);
    float s1 = g0 * __ldg(&wroot2[lane * 2]) + g1 * __ldg(&wroot2[lane * 2 + 1]);
#pragma unroll
    for (int off = 16; off; off >>= 1) {
        s0 += __shfl_xor_sync(0xffffffffu, s0, off);
        s1 += __shfl_xor_sync(0xffffffffu, s1, off);
    }
    if (lane == 0) {
        g_srel[gw] = s0;
        g_gate[gw] = s1 + __ldg(&bg2[0]);
    }
}

__global__ void gather_gate_kernel() {
    int gw = (blockIdx.x * blockDim.x + threadIdx.x) >> 5;
    int lane = threadIdx.x & 31;
    if (gw >= N_NODES) return;
    int s = g_rs[gw], e = g_rs[gw + 1];
    float acc = 0.f;
    for (int i = s + lane; i < e; i += 32) acc += g_srel[__ldg(&g_dst[i])];
#pragma unroll
    for (int off = 16; off; off >>= 1) acc += __shfl_xor_sync(0xffffffffu, acc, off);
    if (lane == 0) g_gate[gw] += acc;
}

// ---------------- per-edge cosine similarity ----------------
__global__ void edge_cos_kernel(const int* __restrict__ row, const int* __restrict__ col,
                                float* __restrict__ wmu) {
    int e = blockIdx.x * blockDim.x + threadIdx.x;
    if (e >= N_EDGES) return;
    int r = __ldg(&row[e]);
    int c = __ldg(&col[e]);
    const float4* a = (const float4*)&g_z[(size_t)r * 64];
    const float4* b = (const float4*)&g_z[(size_t)c * 64];
    float acc = 0.f;
#pragma unroll
    for (int i = 0; i < 16; i++) {
        float4 u = __ldg(a + i), v = __ldg(b + i);
        acc += u.x * v.x + u.y * v.y + u.z * v.z + u.w * v.w;
    }
    wmu[e] = acc / (g_norm[r] * g_norm[c]);
}

// ---------------- gate max (single block) + zero accumulators ----------------
__global__ void max_kernel() {
    __shared__ float sm[1024];
    int t = threadIdx.x;
    float m = -1e30f;
    for (int i = t; i < N_NODES; i += 1024) m = fmaxf(m, g_gate[i]);
    sm[t] = m;
    __syncthreads();
    for (int s = 512; s > 0; s >>= 1) {
        if (t < s) sm[t] = fmaxf(sm[t], sm[t + s]);
        __syncthreads();
    }
    if (t == 0) { g_scal[0] = sm[0]; g_scal[1] = 0.f; }
    if (t < 64) g_pool[t] = 0.f;
}

// ---------------- sum exp + weighted pool ----------------
__global__ void pool_kernel() {
    int t = threadIdx.x;  // 0..63
    int n0 = blockIdx.x * 256;
    int n1 = n0 + 256; if (n1 > N_NODES) n1 = N_NODES;
    float gmax = g_scal[0];
    float acc = 0.f, sacc = 0.f;
    for (int n = n0; n < n1; n++) {
        float w = expf(g_gate[n] - gmax);
        acc += w * g_z[(size_t)n * 64 + t];
        if (t == 0) sacc += w;
    }
    atomicAdd(&g_pool[t], acc);
    if (t == 0) atomicAdd(&g_scal[1], sacc);
}

// ---------------- classifier + final outputs ----------------
__global__ void final_kernel(const float* __restrict__ w_cls1, const float* __restrict__ b_cls1,
                             const float* __restrict__ w_cls2, const float* __restrict__ b_cls2,
                             const float* __restrict__ log_std, float* __restrict__ out) {
    __shared__ float pooled[64], y1s[64], y2s[2];
    int t = threadIdx.x;  // 64
    pooled[t] = g_pool[t] / g_scal[1];
    __syncthreads();
    float acc = __ldg(&b_cls1[t]);
#pragma unroll
    for (int j = 0; j < 64; j++) acc += pooled[j] * __ldg(&w_cls1[t * 64 + j]);
    y1s[t] = lrelu(acc);
    __syncthreads();
    if (t < 2) {
        float a = __ldg(&b_cls2[t]);
#pragma unroll
        for (int j = 0; j < 64; j++) a += y1s[j] * __ldg(&w_cls2[t * 64 + j]);
        y2s[t] = a;
    }
    __syncthreads();
    if (t == 0) {
        float m = fmaxf(y2s[0], y2s[1]);
        float e0 = expf(y2s[0] - m), e1 = expf(y2s[1] - m);
        out[0] = e0 / (e0 + e1);
        out[1] = e1 / (e0 + e1);
        out[2 + N_EDGES] = expf(__ldg(&log_std[0]));
    }
}

// ---------------- launch ----------------
extern "C" void kernel_launch(void* const* d_in, const int* in_sizes, int n_in,
                              void* d_out, int out_size) {
    const float* x        = (const float*)d_in[0];
    const int*   row      = (const int*)d_in[1];
    const int*   col      = (const int*)d_in[2];
    const float* w_rel1   = (const float*)d_in[3];
    const float* w_root1  = (const float*)d_in[4];
    const float* b1       = (const float*)d_in[5];
    const float* w_rel_mu = (const float*)d_in[6];
    const float* w_root_mu= (const float*)d_in[7];
    const float* b_mu     = (const float*)d_in[8];
    const float* w_std    = (const float*)d_in[9];
    const float* b_std    = (const float*)d_in[10];
    const float* w_rel_g1 = (const float*)d_in[11];
    const float* w_root_g1= (const float*)d_in[12];
    const float* b_g1     = (const float*)d_in[13];
    const float* w_rel_g2 = (const float*)d_in[14];
    const float* w_root_g2= (const float*)d_in[15];
    const float* b_g2     = (const float*)d_in[16];
    const float* w_cls1   = (const float*)d_in[17];
    const float* b_cls1   = (const float*)d_in[18];
    const float* w_cls2   = (const float*)d_in[19];
    const float* b_cls2   = (const float*)d_in[20];
    const float* log_std  = (const float*)d_in[21];

    float* out       = (float*)d_out;
    float* out_wmu   = out + 2;
    float* out_z     = out + 3 + N_EDGES;
    float* out_zmu   = out_z + (size_t)N_NODES * 64;
    float* out_zstd  = out_zmu + (size_t)N_NODES * 64;

    const int MB = (N_NODES + 127) / 128;      // 391 row tiles
    const int EB = (N_EDGES + 255) / 256;      // edge blocks
    const int WB = (N_NODES * 32 + 255) / 256; // warp-per-node blocks

    prepack_kernel<<<256, 256>>>(w_rel1, w_root1, w_rel_mu, w_root_mu, w_std, w_rel_g1, w_root_g1);
    hist_kernel<<<EB, 256>>>(row);
    scan_kernel<<<1, 1024>>>();
    fill_kernel<<<EB, 256>>>(row, col);

    // layer 1
    gemm_kernel<1><<<dim3(4, MB), 128>>>(x, b1, nullptr, nullptr);
    gather_h_kernel<<<WB, 256>>>();

    // layer 2 + std head
    gemm_kernel<2><<<dim3(3, MB), 128>>>(nullptr, b_mu, b_std, out_zstd);
    gather_z_kernel<<<WB, 256>>>(out_z, out_zmu);

    // edge cosine similarity
    edge_cos_kernel<<<EB, 256>>>(row, col, out_wmu);

    // gating convs
    gemm_kernel<3><<<dim3(2, MB), 128>>>(nullptr, b_g1, nullptr, nullptr);
    gather_g_kernel<<<WB, 256>>>(w_rel_g2, w_root_g2, b_g2);
    gather_gate_kernel<<<WB, 256>>>();

    // softmax pooling + classifier
    max_kernel<<<1, 1024>>>();
    pool_kernel<<<(N_NODES + 255) / 256, 64>>>();
    final_kernel<<<1, 64>>>(w_cls1, b_cls1, w_cls2, b_cls2, log_std, out);
}

// round 4
// speedup vs baseline: 1.4912x; 1.2911x over previous
#include <cuda_runtime.h>
#include <cuda_bf16.h>
#include <math.h>
#include <stdint.h>

#define N_NODES 50000
#define N_EDGES 800000
// dims: IN=256, EMB1=128, EMB2=64, L1=64

// ---------------- device scratch ----------------
__device__ float g_xr1 [(size_t)N_NODES * 128];   // x @ w_rel1^T
__device__ float g_h   [(size_t)N_NODES * 128];   // root1 + b1 (then unused; bf16 h in gHh/gHl)
__device__ float g_zr  [(size_t)N_NODES * 64];    // h @ w_rel_mu^T
__device__ float g_zbuf[(size_t)N_NODES * 64];    // root_mu + b_mu
__device__ float g_z   [(size_t)N_NODES * 64];    // z = tanh(zbuf + agg)
__device__ float g_gr  [(size_t)N_NODES * 64];
__device__ float g_gbuf[(size_t)N_NODES * 64];
__device__ float g_srel[N_NODES];
__device__ float g_gate[N_NODES];
__device__ float g_norm[N_NODES];
__device__ float g_pool[64];
__device__ float g_scal[2];
// bf16 hi/lo operands
__device__ __nv_bfloat162 gXh[(size_t)N_NODES * 128], gXl[(size_t)N_NODES * 128];
__device__ __nv_bfloat162 gHh[(size_t)N_NODES * 64],  gHl[(size_t)N_NODES * 64];
__device__ __nv_bfloat162 gZh[(size_t)N_NODES * 32],  gZl[(size_t)N_NODES * 32];
__device__ __nv_bfloat16  gW1h[256 * 256], gW1l[256 * 256];
__device__ __nv_bfloat16  gW2h[192 * 128], gW2l[192 * 128];
__device__ __nv_bfloat16  gW3h[128 * 64],  gW3l[128 * 64];
// CSR
__device__ int g_cnt[N_NODES];
__device__ int g_rs[N_NODES + 1];
__device__ int g_fill[N_NODES];
__device__ int g_dst[N_EDGES];

__device__ __forceinline__ float lrelu(float v) { return v > 0.f ? v : 0.2f * v; }
__device__ __forceinline__ void split(float v, __nv_bfloat16& h, __nv_bfloat16& l) {
    h = __float2bfloat16(v);
    l = __float2bfloat16(v - __bfloat162float(h));
}

#define MMA_BF16(c0, c1, c2, c3, a0, a1, a2, a3, b0, b1)                          \
    asm volatile("mma.sync.aligned.m16n8k16.row.col.f32.bf16.bf16.f32 "           \
                 "{%0,%1,%2,%3}, {%4,%5,%6,%7}, {%8,%9}, {%0,%1,%2,%3};"          \
                 : "+f"(c0), "+f"(c1), "+f"(c2), "+f"(c3)                         \
                 : "r"(a0), "r"(a1), "r"(a2), "r"(a3), "r"(b0), "r"(b1))

// ---------------- prepack: weights -> bf16 hi/lo; zero CSR counters ----------------
__global__ void prepack_kernel(const float* __restrict__ wr1, const float* __restrict__ wo1,
                               const float* __restrict__ wrm, const float* __restrict__ wom,
                               const float* __restrict__ wstd,
                               const float* __restrict__ wrg1, const float* __restrict__ wog1) {
    int i = blockIdx.x * blockDim.x + threadIdx.x;  // 0..65535
    float v;
    if (i < 128 * 256)      v = wr1[i];
    else                    v = wo1[i - 128 * 256];
    split(v, gW1h[i], gW1l[i]);
    if (i < 192 * 128) {
        if (i < 64 * 128)        v = wrm[i];
        else if (i < 128 * 128)  v = wom[i - 64 * 128];
        else                     v = wstd[i - 128 * 128];
        split(v, gW2h[i], gW2l[i]);
    }
    if (i < 128 * 64) {
        v = (i < 64 * 64) ? wrg1[i] : wog1[i - 64 * 64];
        split(v, gW3h[i], gW3l[i]);
    }
    if (i < N_NODES) g_cnt[i] = 0;
}

// ---------------- x -> bf16 hi/lo ----------------
__global__ void convx_kernel(const float* __restrict__ x) {
    size_t i = (size_t)blockIdx.x * blockDim.x + threadIdx.x;  // pair index
    if (i >= (size_t)N_NODES * 128) return;
    float2 v = ((const float2*)x)[i];
    __nv_bfloat16 h0, l0, h1, l1;
    split(v.x, h0, l0);
    split(v.y, h1, l1);
    gXh[i] = __nv_bfloat162(h0, h1);
    gXl[i] = __nv_bfloat162(l0, l1);
}

// ---------------- CSR build ----------------
__global__ void hist_kernel(const int* __restrict__ row) {
    int e = blockIdx.x * blockDim.x + threadIdx.x;
    if (e < N_EDGES) atomicAdd(&g_cnt[__ldg(&row[e])], 1);
}

__global__ void scan_kernel() {
    __shared__ int part[1024];
    int t = threadIdx.x;
    const int CH = (N_NODES + 1023) / 1024;
    int base = t * CH;
    int s = 0;
    for (int i = 0; i < CH; i++) {
        int idx = base + i;
        if (idx < N_NODES) s += g_cnt[idx];
    }
    part[t] = s;
    __syncthreads();
    for (int off = 1; off < 1024; off <<= 1) {
        int v = (t >= off) ? part[t - off] : 0;
        __syncthreads();
        part[t] += v;
        __syncthreads();
    }
    int run = (t == 0) ? 0 : part[t - 1];
    for (int i = 0; i < CH; i++) {
        int idx = base + i;
        if (idx < N_NODES) {
            g_rs[idx] = run;
            g_fill[idx] = run;
            run += g_cnt[idx];
        }
    }
    if (t == 1023) g_rs[N_NODES] = part[1023];
}

__global__ void fill_kernel(const int* __restrict__ row, const int* __restrict__ col) {
    int e = blockIdx.x * blockDim.x + threadIdx.x;
    if (e >= N_EDGES) return;
    int pos = atomicAdd(&g_fill[__ldg(&row[e])], 1);
    g_dst[pos] = __ldg(&col[e]);
}

// ---------------- mma.sync bf16 hi/lo GEMM: C[128 x 64] tiles ----------------
// MODE 1: A=x (K=256), NOUT=256: tiles 0,1 -> g_xr1 ; 2,3 -> g_h = v + b1
// MODE 2: A=h (K=128), NOUT=192: 0 -> g_zr ; 1 -> g_zbuf = v+b_mu ; 2 -> exp(tanh(v+b_std))
// MODE 3: A=z (K=64),  NOUT=128: 0 -> g_gr ; 1 -> g_gbuf = v+b_g1
#define APITCH 40
template <int MODE>
__global__ __launch_bounds__(256)
void mma_gemm_kernel(const float* __restrict__ bias0, const float* __restrict__ bias1,
                     float* __restrict__ out_extra) {
    constexpr int K = (MODE == 1) ? 256 : (MODE == 2) ? 128 : 64;
    __shared__ __nv_bfloat16 sAh[128][APITCH], sAl[128][APITCH];
    __shared__ __nv_bfloat16 sBh[64][APITCH],  sBl[64][APITCH];

    const __nv_bfloat16* Ah = (MODE == 1) ? (const __nv_bfloat16*)gXh
                            : (MODE == 2) ? (const __nv_bfloat16*)gHh : (const __nv_bfloat16*)gZh;
    const __nv_bfloat16* Al = (MODE == 1) ? (const __nv_bfloat16*)gXl
                            : (MODE == 2) ? (const __nv_bfloat16*)gHl : (const __nv_bfloat16*)gZl;
    const __nv_bfloat16* Wh = (MODE == 1) ? gW1h : (MODE == 2) ? gW2h : gW3h;
    const __nv_bfloat16* Wl = (MODE == 1) ? gW1l : (MODE == 2) ? gW2l : gW3l;

    const int tid = threadIdx.x;
    const int wid = tid >> 5, lane = tid & 31;
    const int wm = wid & 3, wn = wid >> 2;          // 4 x 2 warp grid
    const int g = lane >> 2, tq = lane & 3;         // quad layout
    const int row0 = blockIdx.y * 128;
    const int col0 = blockIdx.x * 64;
    const int rm = wm * 32, cn = wn * 32;

    float acc[2][4][4];
#pragma unroll
    for (int i = 0; i < 2; i++)
#pragma unroll
        for (int j = 0; j < 4; j++)
#pragma unroll
            for (int p = 0; p < 4; p++) acc[i][j][p] = 0.f;

    for (int k0 = 0; k0 < K; k0 += 32) {
        // stage A tile: 128 rows x 32 k, hi+lo. 512 uint4 chunks each.
#pragma unroll
        for (int i = 0; i < 2; i++) {
            int li = tid + i * 256;          // 0..511
            int r = li >> 2, ch = (li & 3) * 8;
            int grow = row0 + r;
            if (grow >= N_NODES) grow = N_NODES - 1;
            *(uint4*)&sAh[r][ch] = *(const uint4*)&Ah[(size_t)grow * K + k0 + ch];
            *(uint4*)&sAl[r][ch] = *(const uint4*)&Al[(size_t)grow * K + k0 + ch];
        }
        // stage B tile: 64 rows x 32 k. 256 uint4 chunks each.
        {
            int r = tid >> 2, ch = (tid & 3) * 8;
            *(uint4*)&sBh[r][ch] = *(const uint4*)&Wh[(size_t)(col0 + r) * K + k0 + ch];
            *(uint4*)&sBl[r][ch] = *(const uint4*)&Wl[(size_t)(col0 + r) * K + k0 + ch];
        }
        __syncthreads();

#pragma unroll
        for (int ks = 0; ks < 32; ks += 16) {
            uint32_t ah[2][4], al[2][4], bh[4][2], bl[4][2];
#pragma unroll
            for (int i = 0; i < 2; i++) {
                int r = rm + i * 16 + g;
                ah[i][0] = *(const uint32_t*)&sAh[r][ks + tq * 2];
                ah[i][1] = *(const uint32_t*)&sAh[r + 8][ks + tq * 2];
                ah[i][2] = *(const uint32_t*)&sAh[r][ks + tq * 2 + 8];
                ah[i][3] = *(const uint32_t*)&sAh[r + 8][ks + tq * 2 + 8];
                al[i][0] = *(const uint32_t*)&sAl[r][ks + tq * 2];
                al[i][1] = *(const uint32_t*)&sAl[r + 8][ks + tq * 2];
                al[i][2] = *(const uint32_t*)&sAl[r][ks + tq * 2 + 8];
                al[i][3] = *(const uint32_t*)&sAl[r + 8][ks + tq * 2 + 8];
            }
#pragma unroll
            for (int j = 0; j < 4; j++) {
                int n = cn + j * 8 + g;
                bh[j][0] = *(const uint32_t*)&sBh[n][ks + tq * 2];
                bh[j][1] = *(const uint32_t*)&sBh[n][ks + tq * 2 + 8];
                bl[j][0] = *(const uint32_t*)&sBl[n][ks + tq * 2];
                bl[j][1] = *(const uint32_t*)&sBl[n][ks + tq * 2 + 8];
            }
#pragma unroll
            for (int i = 0; i < 2; i++)
#pragma unroll
                for (int j = 0; j < 4; j++) {
                    MMA_BF16(acc[i][j][0], acc[i][j][1], acc[i][j][2], acc[i][j][3],
                             ah[i][0], ah[i][1], ah[i][2], ah[i][3], bh[j][0], bh[j][1]);
                    MMA_BF16(acc[i][j][0], acc[i][j][1], acc[i][j][2], acc[i][j][3],
                             al[i][0], al[i][1], al[i][2], al[i][3], bh[j][0], bh[j][1]);
                    MMA_BF16(acc[i][j][0], acc[i][j][1], acc[i][j][2], acc[i][j][3],
                             ah[i][0], ah[i][1], ah[i][2], ah[i][3], bl[j][0], bl[j][1]);
                }
        }
        __syncthreads();
    }

    // epilogue: thread holds C[row][gcol], C[row][gcol+1] (p=0,1) and row+8 (p=2,3)
#pragma unroll
    for (int i = 0; i < 2; i++) {
#pragma unroll
        for (int half = 0; half < 2; half++) {
            int m = row0 + rm + i * 16 + g + half * 8;
            if (m >= N_NODES) continue;
#pragma unroll
            for (int j = 0; j < 4; j++) {
                int gcol = col0 + cn + j * 8 + tq * 2;
                float2 v = make_float2(acc[i][j][half * 2], acc[i][j][half * 2 + 1]);
                if (MODE == 1) {
                    if (gcol < 128) {
                        *(float2*)&g_xr1[(size_t)m * 128 + gcol] = v;
                    } else {
                        float2 b = *(const float2*)&bias0[gcol - 128];
                        v.x += b.x; v.y += b.y;
                        *(float2*)&g_h[(size_t)m * 128 + gcol - 128] = v;
                    }
                } else if (MODE == 2) {
                    if (gcol < 64) {
                        *(float2*)&g_zr[(size_t)m * 64 + gcol] = v;
                    } else if (gcol < 128) {
                        float2 b = *(const float2*)&bias0[gcol - 64];
                        v.x += b.x; v.y += b.y;
                        *(float2*)&g_zbuf[(size_t)m * 64 + gcol - 64] = v;
                    } else {
                        float2 b = *(const float2*)&bias1[gcol - 128];
                        size_t o = (size_t)m * 64 + gcol - 128;
                        out_extra[o + 0] = expf(tanhf(v.x + b.x));   // scalar: out ptr 4B-aligned
                        out_extra[o + 1] = expf(tanhf(v.y + b.y));
                    }
                } else {
                    if (gcol < 64) {
                        *(float2*)&g_gr[(size_t)m * 64 + gcol] = v;
                    } else {
                        float2 b = *(const float2*)&bias0[gcol - 64];
                        v.x += b.x; v.y += b.y;
                        *(float2*)&g_gbuf[(size_t)m * 64 + gcol - 64] = v;
                    }
                }
            }
        }
    }
}

// ---------------- CSR gathers (warp per node) ----------------
__global__ void gather_h_kernel() {
    int gw = (blockIdx.x * blockDim.x + threadIdx.x) >> 5;
    int lane = threadIdx.x & 31;
    if (gw >= N_NODES) return;
    int s = g_rs[gw], e = g_rs[gw + 1];
    float4 acc = make_float4(0.f, 0.f, 0.f, 0.f);
    for (int i = s; i < e; i++) {
        int c = __ldg(&g_dst[i]);
        float4 v = *(const float4*)&g_xr1[(size_t)c * 128 + lane * 4];
        acc.x += v.x; acc.y += v.y; acc.z += v.z; acc.w += v.w;
    }
    size_t o = (size_t)gw * 128 + lane * 4;
    float4 h = *(const float4*)&g_h[o];
    h.x = lrelu(h.x + acc.x); h.y = lrelu(h.y + acc.y);
    h.z = lrelu(h.z + acc.z); h.w = lrelu(h.w + acc.w);
    __nv_bfloat16 h0, l0, h1, l1, h2, l2, h3, l3;
    split(h.x, h0, l0); split(h.y, h1, l1); split(h.z, h2, l2); split(h.w, h3, l3);
    size_t o2 = (size_t)gw * 64 + lane * 2;
    gHh[o2 + 0] = __nv_bfloat162(h0, h1);
    gHh[o2 + 1] = __nv_bfloat162(h2, h3);
    gHl[o2 + 0] = __nv_bfloat162(l0, l1);
    gHl[o2 + 1] = __nv_bfloat162(l2, l3);
}

__global__ void gather_z_kernel(float* __restrict__ out_z, float* __restrict__ out_zmu) {
    int gw = (blockIdx.x * blockDim.x + threadIdx.x) >> 5;
    int lane = threadIdx.x & 31;
    if (gw >= N_NODES) return;
    int s = g_rs[gw], e = g_rs[gw + 1];
    float a0 = 0.f, a1 = 0.f;
    for (int i = s; i < e; i++) {
        int c = __ldg(&g_dst[i]);
        float2 v = *(const float2*)&g_zr[(size_t)c * 64 + lane * 2];
        a0 += v.x; a1 += v.y;
    }
    size_t o = (size_t)gw * 64 + lane * 2;
    float2 zb = *(const float2*)&g_zbuf[o];
    float z0 = tanhf(zb.x + a0), z1 = tanhf(zb.y + a1);
    *(float2*)&g_z[o] = make_float2(z0, z1);
    out_z[o] = z0; out_z[o + 1] = z1;
    out_zmu[o] = z0; out_zmu[o + 1] = z1;
    __nv_bfloat16 h0, l0, h1, l1;
    split(z0, h0, l0); split(z1, h1, l1);
    size_t o2 = (size_t)gw * 32 + lane;
    gZh[o2] = __nv_bfloat162(h0, h1);
    gZl[o2] = __nv_bfloat162(l0, l1);
    float ss = z0 * z0 + z1 * z1;
#pragma unroll
    for (int off = 16; off; off >>= 1) ss += __shfl_xor_sync(0xffffffffu, ss, off);
    if (lane == 0) g_norm[gw] = fmaxf(sqrtf(ss), 1e-8f);
}

__global__ void gather_g_kernel(const float* __restrict__ wrel2, const float* __restrict__ wroot2,
                                const float* __restrict__ bg2) {
    int gw = (blockIdx.x * blockDim.x + threadIdx.x) >> 5;
    int lane = threadIdx.x & 31;
    if (gw >= N_NODES) return;
    int s = g_rs[gw], e = g_rs[gw + 1];
    float a0 = 0.f, a1 = 0.f;
    for (int i = s; i < e; i++) {
        int c = __ldg(&g_dst[i]);
        float2 v = *(const float2*)&g_gr[(size_t)c * 64 + lane * 2];
        a0 += v.x; a1 += v.y;
    }
    size_t o = (size_t)gw * 64 + lane * 2;
    float2 gb = *(const float2*)&g_gbuf[o];
    float g0 = lrelu(gb.x + a0), g1 = lrelu(gb.y + a1);
    float s0 = g0 * __ldg(&wrel2[lane * 2]) + g1 * __ldg(&wrel2[lane * 2 + 1]);
    float s1 = g0 * __ldg(&wroot2[lane * 2]) + g1 * __ldg(&wroot2[lane * 2 + 1]);
#pragma unroll
    for (int off = 16; off; off >>= 1) {
        s0 += __shfl_xor_sync(0xffffffffu, s0, off);
        s1 += __shfl_xor_sync(0xffffffffu, s1, off);
    }
    if (lane == 0) {
        g_srel[gw] = s0;
        g_gate[gw] = s1 + __ldg(&bg2[0]);
    }
}

__global__ void gather_gate_kernel() {
    int gw = (blockIdx.x * blockDim.x + threadIdx.x) >> 5;
    int lane = threadIdx.x & 31;
    if (gw >= N_NODES) return;
    int s = g_rs[gw], e = g_rs[gw + 1];
    float acc = 0.f;
    for (int i = s + lane; i < e; i += 32) acc += g_srel[__ldg(&g_dst[i])];
#pragma unroll
    for (int off = 16; off; off >>= 1) acc += __shfl_xor_sync(0xffffffffu, acc, off);
    if (lane == 0) g_gate[gw] += acc;
}

// ---------------- per-edge cosine similarity ----------------
__global__ void edge_cos_kernel(const int* __restrict__ row, const int* __restrict__ col,
                                float* __restrict__ wmu) {
    int e = blockIdx.x * blockDim.x + threadIdx.x;
    if (e >= N_EDGES) return;
    int r = __ldg(&row[e]);
    int c = __ldg(&col[e]);
    const float4* a = (const float4*)&g_z[(size_t)r * 64];
    const float4* b = (const float4*)&g_z[(size_t)c * 64];
    float acc = 0.f;
#pragma unroll
    for (int i = 0; i < 16; i++) {
        float4 u = __ldg(a + i), v = __ldg(b + i);
        acc += u.x * v.x + u.y * v.y + u.z * v.z + u.w * v.w;
    }
    wmu[e] = acc / (g_norm[r] * g_norm[c]);
}

// ---------------- gate max + zero accumulators ----------------
__global__ void max_kernel() {
    __shared__ float sm[1024];
    int t = threadIdx.x;
    float m = -1e30f;
    for (int i = t; i < N_NODES; i += 1024) m = fmaxf(m, g_gate[i]);
    sm[t] = m;
    __syncthreads();
    for (int s = 512; s > 0; s >>= 1) {
        if (t < s) sm[t] = fmaxf(sm[t], sm[t + s]);
        __syncthreads();
    }
    if (t == 0) { g_scal[0] = sm[0]; g_scal[1] = 0.f; }
    if (t < 64) g_pool[t] = 0.f;
}

// ---------------- sum exp + weighted pool ----------------
__global__ void pool_kernel() {
    int t = threadIdx.x;  // 0..63
    int n0 = blockIdx.x * 256;
    int n1 = n0 + 256; if (n1 > N_NODES) n1 = N_NODES;
    float gmax = g_scal[0];
    float acc = 0.f, sacc = 0.f;
    for (int n = n0; n < n1; n++) {
        float w = expf(g_gate[n] - gmax);
        acc += w * g_z[(size_t)n * 64 + t];
        if (t == 0) sacc += w;
    }
    atomicAdd(&g_pool[t], acc);
    if (t == 0) atomicAdd(&g_scal[1], sacc);
}

// ---------------- classifier + final outputs ----------------
__global__ void final_kernel(const float* __restrict__ w_cls1, const float* __restrict__ b_cls1,
                             const float* __restrict__ w_cls2, const float* __restrict__ b_cls2,
                             const float* __restrict__ log_std, float* __restrict__ out) {
    __shared__ float pooled[64], y1s[64], y2s[2];
    int t = threadIdx.x;  // 64
    pooled[t] = g_pool[t] / g_scal[1];
    __syncthreads();
    float acc = __ldg(&b_cls1[t]);
#pragma unroll
    for (int j = 0; j < 64; j++) acc += pooled[j] * __ldg(&w_cls1[t * 64 + j]);
    y1s[t] = lrelu(acc);
    __syncthreads();
    if (t < 2) {
        float a = __ldg(&b_cls2[t]);
#pragma unroll
        for (int j = 0; j < 64; j++) a += y1s[j] * __ldg(&w_cls2[t * 64 + j]);
        y2s[t] = a;
    }
    __syncthreads();
    if (t == 0) {
        float m = fmaxf(y2s[0], y2s[1]);
        float e0 = expf(y2s[0] - m), e1 = expf(y2s[1] - m);
        out[0] = e0 / (e0 + e1);
        out[1] = e1 / (e0 + e1);
        out[2 + N_EDGES] = expf(__ldg(&log_std[0]));
    }
}

// ---------------- launch ----------------
extern "C" void kernel_launch(void* const* d_in, const int* in_sizes, int n_in,
                              void* d_out, int out_size) {
    const float* x        = (const float*)d_in[0];
    const int*   row      = (const int*)d_in[1];
    const int*   col      = (const int*)d_in[2];
    const float* w_rel1   = (const float*)d_in[3];
    const float* w_root1  = (const float*)d_in[4];
    const float* b1       = (const float*)d_in[5];
    const float* w_rel_mu = (const float*)d_in[6];
    const float* w_root_mu= (const float*)d_in[7];
    const float* b_mu     = (const float*)d_in[8];
    const float* w_std    = (const float*)d_in[9];
    const float* b_std    = (const float*)d_in[10];
    const float* w_rel_g1 = (const float*)d_in[11];
    const float* w_root_g1= (const float*)d_in[12];
    const float* b_g1     = (const float*)d_in[13];
    const float* w_rel_g2 = (const float*)d_in[14];
    const float* w_root_g2= (const float*)d_in[15];
    const float* b_g2     = (const float*)d_in[16];
    const float* w_cls1   = (const float*)d_in[17];
    const float* b_cls1   = (const float*)d_in[18];
    const float* w_cls2   = (const float*)d_in[19];
    const float* b_cls2   = (const float*)d_in[20];
    const float* log_std  = (const float*)d_in[21];

    float* out       = (float*)d_out;
    float* out_wmu   = out + 2;
    float* out_z     = out + 3 + N_EDGES;
    float* out_zmu   = out_z + (size_t)N_NODES * 64;
    float* out_zstd  = out_zmu + (size_t)N_NODES * 64;

    const int MB = (N_NODES + 127) / 128;      // 391 row tiles
    const int EB = (N_EDGES + 255) / 256;
    const int WB = (N_NODES * 32 + 255) / 256;

    prepack_kernel<<<256, 256>>>(w_rel1, w_root1, w_rel_mu, w_root_mu, w_std, w_rel_g1, w_root_g1);
    convx_kernel<<<(N_NODES * 128 + 255) / 256, 256>>>(x);
    hist_kernel<<<EB, 256>>>(row);
    scan_kernel<<<1, 1024>>>();
    fill_kernel<<<EB, 256>>>(row, col);

    // layer 1
    mma_gemm_kernel<1><<<dim3(4, MB), 256>>>(b1, nullptr, nullptr);
    gather_h_kernel<<<WB, 256>>>();

    // layer 2 + std head
    mma_gemm_kernel<2><<<dim3(3, MB), 256>>>(b_mu, b_std, out_zstd);
    gather_z_kernel<<<WB, 256>>>(out_z, out_zmu);

    // edge cosine similarity
    edge_cos_kernel<<<EB, 256>>>(row, col, out_wmu);

    // gating convs
    mma_gemm_kernel<3><<<dim3(2, MB), 256>>>(b_g1, nullptr, nullptr);
    gather_g_kernel<<<WB, 256>>>(w_rel_g2, w_root_g2, b_g2);
    gather_gate_kernel<<<WB, 256>>>();

    // softmax pooling + classifier
    max_kernel<<<1, 1024>>>();
    pool_kernel<<<(N_NODES + 255) / 256, 64>>>();
    final_kernel<<<1, 64>>>(w_cls1, b_cls1, w_cls2, b_cls2, log_std, out);
}

// round 5
// speedup vs baseline: 1.7435x; 1.1692x over previous
#include <cuda_runtime.h>
#include <cuda_bf16.h>
#include <math.h>
#include <stdint.h>

#define N_NODES 50000
#define N_EDGES 800000
#define NB_SCAN 196   // ceil(50000 / 256)
// dims: IN=256, EMB1=128, EMB2=64, L1=64

// ---------------- device scratch ----------------
__device__ float g_xr1 [(size_t)N_NODES * 128];
__device__ float g_h   [(size_t)N_NODES * 128];
__device__ float g_zr  [(size_t)N_NODES * 64];
__device__ float g_zbuf[(size_t)N_NODES * 64];
__device__ float g_z   [(size_t)N_NODES * 64];
__device__ float g_gr  [(size_t)N_NODES * 64];
__device__ float g_gbuf[(size_t)N_NODES * 64];
__device__ float g_srel[N_NODES];
__device__ float g_gate[N_NODES];
__device__ float g_norm[N_NODES];
__device__ float g_pool[64];
__device__ float g_scal[2];
__device__ unsigned int g_gmax_u;
// bf16 hi/lo operands
__device__ __nv_bfloat162 gXh[(size_t)N_NODES * 128], gXl[(size_t)N_NODES * 128];
__device__ __nv_bfloat162 gHh[(size_t)N_NODES * 64],  gHl[(size_t)N_NODES * 64];
__device__ __nv_bfloat162 gZh[(size_t)N_NODES * 32],  gZl[(size_t)N_NODES * 32];
__device__ __nv_bfloat16  gW1h[256 * 256], gW1l[256 * 256];
__device__ __nv_bfloat16  gW2h[192 * 128], gW2l[192 * 128];
__device__ __nv_bfloat16  gW3h[128 * 64],  gW3l[128 * 64];
// CSR
__device__ int g_cnt[N_NODES];
__device__ int g_rs[N_NODES + 1];
__device__ int g_fill[N_NODES];
__device__ int g_dst[N_EDGES];
__device__ int g_bsum[NB_SCAN];
__device__ int g_boff[NB_SCAN];

__device__ __forceinline__ float lrelu(float v) { return v > 0.f ? v : 0.2f * v; }
__device__ __forceinline__ void split(float v, __nv_bfloat16& h, __nv_bfloat16& l) {
    h = __float2bfloat16(v);
    l = __float2bfloat16(v - __bfloat162float(h));
}
__device__ __forceinline__ unsigned int enc_f(float f) {
    unsigned int b = __float_as_uint(f);
    return (b & 0x80000000u) ? ~b : (b | 0x80000000u);
}
__device__ __forceinline__ float dec_f(unsigned int u) {
    return (u & 0x80000000u) ? __uint_as_float(u & 0x7fffffffu) : __uint_as_float(~u);
}

#define MMA_BF16(c0, c1, c2, c3, a0, a1, a2, a3, b0, b1)                          \
    asm volatile("mma.sync.aligned.m16n8k16.row.col.f32.bf16.bf16.f32 "           \
                 "{%0,%1,%2,%3}, {%4,%5,%6,%7}, {%8,%9}, {%0,%1,%2,%3};"          \
                 : "+f"(c0), "+f"(c1), "+f"(c2), "+f"(c3)                         \
                 : "r"(a0), "r"(a1), "r"(a2), "r"(a3), "r"(b0), "r"(b1))

// ---------------- prepack: weights -> bf16 hi/lo; zero accumulators ----------------
__global__ void prepack_kernel(const float* __restrict__ wr1, const float* __restrict__ wo1,
                               const float* __restrict__ wrm, const float* __restrict__ wom,
                               const float* __restrict__ wstd,
                               const float* __restrict__ wrg1, const float* __restrict__ wog1) {
    int i = blockIdx.x * blockDim.x + threadIdx.x;  // 0..65535
    float v;
    if (i < 128 * 256)      v = wr1[i];
    else                    v = wo1[i - 128 * 256];
    split(v, gW1h[i], gW1l[i]);
    if (i < 192 * 128) {
        if (i < 64 * 128)        v = wrm[i];
        else if (i < 128 * 128)  v = wom[i - 64 * 128];
        else                     v = wstd[i - 128 * 128];
        split(v, gW2h[i], gW2l[i]);
    }
    if (i < 128 * 64) {
        v = (i < 64 * 64) ? wrg1[i] : wog1[i - 64 * 64];
        split(v, gW3h[i], gW3l[i]);
    }
    if (i < 64) g_pool[i] = 0.f;
    if (i == 0) { g_scal[1] = 0.f; g_gmax_u = 0u; }
}

// ---------------- x -> bf16 hi/lo ----------------
__global__ void convx_kernel(const float* __restrict__ x) {
    size_t i = (size_t)blockIdx.x * blockDim.x + threadIdx.x;
    if (i >= (size_t)N_NODES * 128) return;
    float2 v = ((const float2*)x)[i];
    __nv_bfloat16 h0, l0, h1, l1;
    split(v.x, h0, l0);
    split(v.y, h1, l1);
    gXh[i] = __nv_bfloat162(h0, h1);
    gXl[i] = __nv_bfloat162(l0, l1);
}

// ---------------- CSR build (parallel scan) ----------------
__global__ void zero_cnt_kernel() {
    int i = blockIdx.x * blockDim.x + threadIdx.x;
    if (i < N_NODES) g_cnt[i] = 0;
}

__global__ void hist_kernel(const int* __restrict__ row) {
    int e = blockIdx.x * blockDim.x + threadIdx.x;
    if (e < N_EDGES) atomicAdd(&g_cnt[__ldg(&row[e])], 1);
}

__global__ void bsum_kernel() {
    __shared__ int sm[256];
    int t = threadIdx.x;
    int idx = blockIdx.x * 256 + t;
    sm[t] = (idx < N_NODES) ? g_cnt[idx] : 0;
    __syncthreads();
    for (int s = 128; s > 0; s >>= 1) {
        if (t < s) sm[t] += sm[t + s];
        __syncthreads();
    }
    if (t == 0) g_bsum[blockIdx.x] = sm[0];
}

__global__ void scanp_kernel() {
    __shared__ int sm[256];
    int t = threadIdx.x;
    int v = (t < NB_SCAN) ? g_bsum[t] : 0;
    sm[t] = v;
    __syncthreads();
    for (int off = 1; off < 256; off <<= 1) {
        int u = (t >= off) ? sm[t - off] : 0;
        __syncthreads();
        sm[t] += u;
        __syncthreads();
    }
    if (t < NB_SCAN) g_boff[t] = sm[t] - v;       // exclusive
    if (t == NB_SCAN - 1) g_rs[N_NODES] = sm[t];  // total
}

__global__ void lscan_kernel() {
    __shared__ int sm[256];
    int t = threadIdx.x;
    int idx = blockIdx.x * 256 + t;
    int v = (idx < N_NODES) ? g_cnt[idx] : 0;
    sm[t] = v;
    __syncthreads();
    for (int off = 1; off < 256; off <<= 1) {
        int u = (t >= off) ? sm[t - off] : 0;
        __syncthreads();
        sm[t] += u;
        __syncthreads();
    }
    if (idx < N_NODES) {
        int r = g_boff[blockIdx.x] + sm[t] - v;   // exclusive global offset
        g_rs[idx] = r;
        g_fill[idx] = r;
    }
}

__global__ void fill_kernel(const int* __restrict__ row, const int* __restrict__ col) {
    int e = blockIdx.x * blockDim.x + threadIdx.x;
    if (e >= N_EDGES) return;
    int pos = atomicAdd(&g_fill[__ldg(&row[e])], 1);
    g_dst[pos] = __ldg(&col[e]);
}

// ---------------- mma.sync bf16 hi/lo GEMM: C[128 x 64] tiles ----------------
#define APITCH 40
template <int MODE>
__global__ __launch_bounds__(256)
void mma_gemm_kernel(const float* __restrict__ bias0, const float* __restrict__ bias1,
                     float* __restrict__ out_extra) {
    constexpr int K = (MODE == 1) ? 256 : (MODE == 2) ? 128 : 64;
    __shared__ __nv_bfloat16 sAh[128][APITCH], sAl[128][APITCH];
    __shared__ __nv_bfloat16 sBh[64][APITCH],  sBl[64][APITCH];

    const __nv_bfloat16* Ah = (MODE == 1) ? (const __nv_bfloat16*)gXh
                            : (MODE == 2) ? (const __nv_bfloat16*)gHh : (const __nv_bfloat16*)gZh;
    const __nv_bfloat16* Al = (MODE == 1) ? (const __nv_bfloat16*)gXl
                            : (MODE == 2) ? (const __nv_bfloat16*)gHl : (const __nv_bfloat16*)gZl;
    const __nv_bfloat16* Wh = (MODE == 1) ? gW1h : (MODE == 2) ? gW2h : gW3h;
    const __nv_bfloat16* Wl = (MODE == 1) ? gW1l : (MODE == 2) ? gW2l : gW3l;

    const int tid = threadIdx.x;
    const int wid = tid >> 5, lane = tid & 31;
    const int wm = wid & 3, wn = wid >> 2;
    const int g = lane >> 2, tq = lane & 3;
    const int row0 = blockIdx.y * 128;
    const int col0 = blockIdx.x * 64;
    const int rm = wm * 32, cn = wn * 32;

    float acc[2][4][4];
#pragma unroll
    for (int i = 0; i < 2; i++)
#pragma unroll
        for (int j = 0; j < 4; j++)
#pragma unroll
            for (int p = 0; p < 4; p++) acc[i][j][p] = 0.f;

    for (int k0 = 0; k0 < K; k0 += 32) {
#pragma unroll
        for (int i = 0; i < 2; i++) {
            int li = tid + i * 256;
            int r = li >> 2, ch = (li & 3) * 8;
            int grow = row0 + r;
            if (grow >= N_NODES) grow = N_NODES - 1;
            *(uint4*)&sAh[r][ch] = *(const uint4*)&Ah[(size_t)grow * K + k0 + ch];
            *(uint4*)&sAl[r][ch] = *(const uint4*)&Al[(size_t)grow * K + k0 + ch];
        }
        {
            int r = tid >> 2, ch = (tid & 3) * 8;
            *(uint4*)&sBh[r][ch] = *(const uint4*)&Wh[(size_t)(col0 + r) * K + k0 + ch];
            *(uint4*)&sBl[r][ch] = *(const uint4*)&Wl[(size_t)(col0 + r) * K + k0 + ch];
        }
        __syncthreads();

#pragma unroll
        for (int ks = 0; ks < 32; ks += 16) {
            uint32_t ah[2][4], al[2][4], bh[4][2], bl[4][2];
#pragma unroll
            for (int i = 0; i < 2; i++) {
                int r = rm + i * 16 + g;
                ah[i][0] = *(const uint32_t*)&sAh[r][ks + tq * 2];
                ah[i][1] = *(const uint32_t*)&sAh[r + 8][ks + tq * 2];
                ah[i][2] = *(const uint32_t*)&sAh[r][ks + tq * 2 + 8];
                ah[i][3] = *(const uint32_t*)&sAh[r + 8][ks + tq * 2 + 8];
                al[i][0] = *(const uint32_t*)&sAl[r][ks + tq * 2];
                al[i][1] = *(const uint32_t*)&sAl[r + 8][ks + tq * 2];
                al[i][2] = *(const uint32_t*)&sAl[r][ks + tq * 2 + 8];
                al[i][3] = *(const uint32_t*)&sAl[r + 8][ks + tq * 2 + 8];
            }
#pragma unroll
            for (int j = 0; j < 4; j++) {
                int n = cn + j * 8 + g;
                bh[j][0] = *(const uint32_t*)&sBh[n][ks + tq * 2];
                bh[j][1] = *(const uint32_t*)&sBh[n][ks + tq * 2 + 8];
                bl[j][0] = *(const uint32_t*)&sBl[n][ks + tq * 2];
                bl[j][1] = *(const uint32_t*)&sBl[n][ks + tq * 2 + 8];
            }
#pragma unroll
            for (int i = 0; i < 2; i++)
#pragma unroll
                for (int j = 0; j < 4; j++) {
                    MMA_BF16(acc[i][j][0], acc[i][j][1], acc[i][j][2], acc[i][j][3],
                             ah[i][0], ah[i][1], ah[i][2], ah[i][3], bh[j][0], bh[j][1]);
                    MMA_BF16(acc[i][j][0], acc[i][j][1], acc[i][j][2], acc[i][j][3],
                             al[i][0], al[i][1], al[i][2], al[i][3], bh[j][0], bh[j][1]);
                    MMA_BF16(acc[i][j][0], acc[i][j][1], acc[i][j][2], acc[i][j][3],
                             ah[i][0], ah[i][1], ah[i][2], ah[i][3], bl[j][0], bl[j][1]);
                }
        }
        __syncthreads();
    }

#pragma unroll
    for (int i = 0; i < 2; i++) {
#pragma unroll
        for (int half = 0; half < 2; half++) {
            int m = row0 + rm + i * 16 + g + half * 8;
            if (m >= N_NODES) continue;
#pragma unroll
            for (int j = 0; j < 4; j++) {
                int gcol = col0 + cn + j * 8 + tq * 2;
                float2 v = make_float2(acc[i][j][half * 2], acc[i][j][half * 2 + 1]);
                if (MODE == 1) {
                    if (gcol < 128) {
                        *(float2*)&g_xr1[(size_t)m * 128 + gcol] = v;
                    } else {
                        float2 b = *(const float2*)&bias0[gcol - 128];
                        v.x += b.x; v.y += b.y;
                        *(float2*)&g_h[(size_t)m * 128 + gcol - 128] = v;
                    }
                } else if (MODE == 2) {
                    if (gcol < 64) {
                        *(float2*)&g_zr[(size_t)m * 64 + gcol] = v;
                    } else if (gcol < 128) {
                        float2 b = *(const float2*)&bias0[gcol - 64];
                        v.x += b.x; v.y += b.y;
                        *(float2*)&g_zbuf[(size_t)m * 64 + gcol - 64] = v;
                    } else {
                        float2 b = *(const float2*)&bias1[gcol - 128];
                        size_t o = (size_t)m * 64 + gcol - 128;
                        out_extra[o + 0] = expf(tanhf(v.x + b.x));
                        out_extra[o + 1] = expf(tanhf(v.y + b.y));
                    }
                } else {
                    if (gcol < 64) {
                        *(float2*)&g_gr[(size_t)m * 64 + gcol] = v;
                    } else {
                        float2 b = *(const float2*)&bias0[gcol - 64];
                        v.x += b.x; v.y += b.y;
                        *(float2*)&g_gbuf[(size_t)m * 64 + gcol - 64] = v;
                    }
                }
            }
        }
    }
}

// ---------------- CSR gathers (warp per node) ----------------
__global__ void gather_h_kernel() {
    int gw = (blockIdx.x * blockDim.x + threadIdx.x) >> 5;
    int lane = threadIdx.x & 31;
    if (gw >= N_NODES) return;
    int s = g_rs[gw], e = g_rs[gw + 1];
    float4 acc = make_float4(0.f, 0.f, 0.f, 0.f);
    for (int i = s; i < e; i++) {
        int c = __ldg(&g_dst[i]);
        float4 v = *(const float4*)&g_xr1[(size_t)c * 128 + lane * 4];
        acc.x += v.x; acc.y += v.y; acc.z += v.z; acc.w += v.w;
    }
    size_t o = (size_t)gw * 128 + lane * 4;
    float4 h = *(const float4*)&g_h[o];
    h.x = lrelu(h.x + acc.x); h.y = lrelu(h.y + acc.y);
    h.z = lrelu(h.z + acc.z); h.w = lrelu(h.w + acc.w);
    __nv_bfloat16 h0, l0, h1, l1, h2, l2, h3, l3;
    split(h.x, h0, l0); split(h.y, h1, l1); split(h.z, h2, l2); split(h.w, h3, l3);
    size_t o2 = (size_t)gw * 64 + lane * 2;
    gHh[o2 + 0] = __nv_bfloat162(h0, h1);
    gHh[o2 + 1] = __nv_bfloat162(h2, h3);
    gHl[o2 + 0] = __nv_bfloat162(l0, l1);
    gHl[o2 + 1] = __nv_bfloat162(l2, l3);
}

__global__ void gather_z_kernel(float* __restrict__ out_z, float* __restrict__ out_zmu) {
    int gw = (blockIdx.x * blockDim.x + threadIdx.x) >> 5;
    int lane = threadIdx.x & 31;
    if (gw >= N_NODES) return;
    int s = g_rs[gw], e = g_rs[gw + 1];
    float a0 = 0.f, a1 = 0.f;
    for (int i = s; i < e; i++) {
        int c = __ldg(&g_dst[i]);
        float2 v = *(const float2*)&g_zr[(size_t)c * 64 + lane * 2];
        a0 += v.x; a1 += v.y;
    }
    size_t o = (size_t)gw * 64 + lane * 2;
    float2 zb = *(const float2*)&g_zbuf[o];
    float z0 = tanhf(zb.x + a0), z1 = tanhf(zb.y + a1);
    *(float2*)&g_z[o] = make_float2(z0, z1);
    out_z[o] = z0; out_z[o + 1] = z1;
    out_zmu[o] = z0; out_zmu[o + 1] = z1;
    __nv_bfloat16 h0, l0, h1, l1;
    split(z0, h0, l0); split(z1, h1, l1);
    size_t o2 = (size_t)gw * 32 + lane;
    gZh[o2] = __nv_bfloat162(h0, h1);
    gZl[o2] = __nv_bfloat162(l0, l1);
    float ss = z0 * z0 + z1 * z1;
#pragma unroll
    for (int off = 16; off; off >>= 1) ss += __shfl_xor_sync(0xffffffffu, ss, off);
    if (lane == 0) g_norm[gw] = fmaxf(sqrtf(ss), 1e-8f);
}

__global__ void gather_g_kernel(const float* __restrict__ wrel2, const float* __restrict__ wroot2,
                                const float* __restrict__ bg2) {
    int gw = (blockIdx.x * blockDim.x + threadIdx.x) >> 5;
    int lane = threadIdx.x & 31;
    if (gw >= N_NODES) return;
    int s = g_rs[gw], e = g_rs[gw + 1];
    float a0 = 0.f, a1 = 0.f;
    for (int i = s; i < e; i++) {
        int c = __ldg(&g_dst[i]);
        float2 v = *(const float2*)&g_gr[(size_t)c * 64 + lane * 2];
        a0 += v.x; a1 += v.y;
    }
    size_t o = (size_t)gw * 64 + lane * 2;
    float2 gb = *(const float2*)&g_gbuf[o];
    float g0 = lrelu(gb.x + a0), g1 = lrelu(gb.y + a1);
    float s0 = g0 * __ldg(&wrel2[lane * 2]) + g1 * __ldg(&wrel2[lane * 2 + 1]);
    float s1 = g0 * __ldg(&wroot2[lane * 2]) + g1 * __ldg(&wroot2[lane * 2 + 1]);
#pragma unroll
    for (int off = 16; off; off >>= 1) {
        s0 += __shfl_xor_sync(0xffffffffu, s0, off);
        s1 += __shfl_xor_sync(0xffffffffu, s1, off);
    }
    if (lane == 0) {
        g_srel[gw] = s0;
        g_gate[gw] = s1 + __ldg(&bg2[0]);
    }
}

__global__ void gather_gate_kernel() {
    int gw = (blockIdx.x * blockDim.x + threadIdx.x) >> 5;
    int lane = threadIdx.x & 31;
    if (gw >= N_NODES) return;
    int s = g_rs[gw], e = g_rs[gw + 1];
    float acc = 0.f;
    for (int i = s + lane; i < e; i += 32) acc += g_srel[__ldg(&g_dst[i])];
#pragma unroll
    for (int off = 16; off; off >>= 1) acc += __shfl_xor_sync(0xffffffffu, acc, off);
    if (lane == 0) {
        float gate = g_gate[gw] + acc;
        g_gate[gw] = gate;
        atomicMax(&g_gmax_u, enc_f(gate));
    }
}

// ---------------- per-edge cosine similarity ----------------
__global__ void edge_cos_kernel(const int* __restrict__ row, const int* __restrict__ col,
                                float* __restrict__ wmu) {
    int e = blockIdx.x * blockDim.x + threadIdx.x;
    if (e >= N_EDGES) return;
    int r = __ldg(&row[e]);
    int c = __ldg(&col[e]);
    const float4* a = (const float4*)&g_z[(size_t)r * 64];
    const float4* b = (const float4*)&g_z[(size_t)c * 64];
    float acc = 0.f;
#pragma unroll
    for (int i = 0; i < 16; i++) {
        float4 u = __ldg(a + i), v = __ldg(b + i);
        acc += u.x * v.x + u.y * v.y + u.z * v.z + u.w * v.w;
    }
    wmu[e] = acc / (g_norm[r] * g_norm[c]);
}

// ---------------- sum exp + weighted pool ----------------
__global__ void pool_kernel() {
    int t = threadIdx.x;  // 0..63
    int n0 = blockIdx.x * 256;
    int n1 = n0 + 256; if (n1 > N_NODES) n1 = N_NODES;
    float gmax = dec_f(g_gmax_u);
    float acc = 0.f, sacc = 0.f;
    for (int n = n0; n < n1; n++) {
        float w = expf(g_gate[n] - gmax);
        acc += w * g_z[(size_t)n * 64 + t];
        if (t == 0) sacc += w;
    }
    atomicAdd(&g_pool[t], acc);
    if (t == 0) atomicAdd(&g_scal[1], sacc);
}

// ---------------- classifier + final outputs ----------------
__global__ void final_kernel(const float* __restrict__ w_cls1, const float* __restrict__ b_cls1,
                             const float* __restrict__ w_cls2, const float* __restrict__ b_cls2,
                             const float* __restrict__ log_std, float* __restrict__ out) {
    __shared__ float pooled[64], y1s[64], y2s[2];
    int t = threadIdx.x;  // 64
    pooled[t] = g_pool[t] / g_scal[1];
    __syncthreads();
    float acc = __ldg(&b_cls1[t]);
#pragma unroll
    for (int j = 0; j < 64; j++) acc += pooled[j] * __ldg(&w_cls1[t * 64 + j]);
    y1s[t] = lrelu(acc);
    __syncthreads();
    if (t < 2) {
        float a = __ldg(&b_cls2[t]);
#pragma unroll
        for (int j = 0; j < 64; j++) a += y1s[j] * __ldg(&w_cls2[t * 64 + j]);
        y2s[t] = a;
    }
    __syncthreads();
    if (t == 0) {
        float m = fmaxf(y2s[0], y2s[1]);
        float e0 = expf(y2s[0] - m), e1 = expf(y2s[1] - m);
        out[0] = e0 / (e0 + e1);
        out[1] = e1 / (e0 + e1);
        out[2 + N_EDGES] = expf(__ldg(&log_std[0]));
    }
}

// ---------------- launch ----------------
extern "C" void kernel_launch(void* const* d_in, const int* in_sizes, int n_in,
                              void* d_out, int out_size) {
    const float* x        = (const float*)d_in[0];
    const int*   row      = (const int*)d_in[1];
    const int*   col      = (const int*)d_in[2];
    const float* w_rel1   = (const float*)d_in[3];
    const float* w_root1  = (const float*)d_in[4];
    const float* b1       = (const float*)d_in[5];
    const float* w_rel_mu = (const float*)d_in[6];
    const float* w_root_mu= (const float*)d_in[7];
    const float* b_mu     = (const float*)d_in[8];
    const float* w_std    = (const float*)d_in[9];
    const float* b_std    = (const float*)d_in[10];
    const float* w_rel_g1 = (const float*)d_in[11];
    const float* w_root_g1= (const float*)d_in[12];
    const float* b_g1     = (const float*)d_in[13];
    const float* w_rel_g2 = (const float*)d_in[14];
    const float* w_root_g2= (const float*)d_in[15];
    const float* b_g2     = (const float*)d_in[16];
    const float* w_cls1   = (const float*)d_in[17];
    const float* b_cls1   = (const float*)d_in[18];
    const float* w_cls2   = (const float*)d_in[19];
    const float* b_cls2   = (const float*)d_in[20];
    const float* log_std  = (const float*)d_in[21];

    float* out       = (float*)d_out;
    float* out_wmu   = out + 2;
    float* out_z     = out + 3 + N_EDGES;
    float* out_zmu   = out_z + (size_t)N_NODES * 64;
    float* out_zstd  = out_zmu + (size_t)N_NODES * 64;

    const int MB = (N_NODES + 127) / 128;
    const int EB = (N_EDGES + 255) / 256;
    const int WB = (N_NODES * 32 + 255) / 256;
    const int NBZ = (N_NODES + 255) / 256;   // = NB_SCAN

    // side stream + fork/join events (handles only; created once)
    static cudaStream_t s1 = nullptr;
    static cudaEvent_t ev_root = nullptr, ev_csr = nullptr, ev_z = nullptr, ev_cos = nullptr;
    if (s1 == nullptr) {
        cudaStreamCreateWithFlags(&s1, cudaStreamNonBlocking);
        cudaEventCreateWithFlags(&ev_root, cudaEventDisableTiming);
        cudaEventCreateWithFlags(&ev_csr, cudaEventDisableTiming);
        cudaEventCreateWithFlags(&ev_z, cudaEventDisableTiming);
        cudaEventCreateWithFlags(&ev_cos, cudaEventDisableTiming);
    }

    // ---- fork 1: CSR build on s1 || prepack/convx/gemm1 on main ----
    cudaEventRecord(ev_root, 0);
    cudaStreamWaitEvent(s1, ev_root, 0);

    zero_cnt_kernel<<<NBZ, 256, 0, s1>>>();
    hist_kernel<<<EB, 256, 0, s1>>>(row);
    bsum_kernel<<<NB_SCAN, 256, 0, s1>>>();
    scanp_kernel<<<1, 256, 0, s1>>>();
    lscan_kernel<<<NB_SCAN, 256, 0, s1>>>();
    fill_kernel<<<EB, 256, 0, s1>>>(row, col);
    cudaEventRecord(ev_csr, s1);

    prepack_kernel<<<256, 256>>>(w_rel1, w_root1, w_rel_mu, w_root_mu, w_std, w_rel_g1, w_root_g1);
    convx_kernel<<<(N_NODES * 128 + 255) / 256, 256>>>(x);
    mma_gemm_kernel<1><<<dim3(4, MB), 256>>>(b1, nullptr, nullptr);

    cudaStreamWaitEvent(0, ev_csr, 0);   // join: gather needs CSR
    gather_h_kernel<<<WB, 256>>>();

    // layer 2 + std head
    mma_gemm_kernel<2><<<dim3(3, MB), 256>>>(b_mu, b_std, out_zstd);
    gather_z_kernel<<<WB, 256>>>(out_z, out_zmu);

    // ---- fork 2: edge cosine on s1 || gating chain on main ----
    cudaEventRecord(ev_z, 0);
    cudaStreamWaitEvent(s1, ev_z, 0);
    edge_cos_kernel<<<EB, 256, 0, s1>>>(row, col, out_wmu);
    cudaEventRecord(ev_cos, s1);

    mma_gemm_kernel<3><<<dim3(2, MB), 256>>>(b_g1, nullptr, nullptr);
    gather_g_kernel<<<WB, 256>>>(w_rel_g2, w_root_g2, b_g2);
    gather_gate_kernel<<<WB, 256>>>();
    pool_kernel<<<NBZ, 64>>>();

    cudaStreamWaitEvent(0, ev_cos, 0);   // join before final
    final_kernel<<<1, 64>>>(w_cls1, b_cls1, w_cls2, b_cls2, log_std, out);
}